// round 8
// baseline (speedup 1.0000x reference)
#include <cuda_runtime.h>

// QuixerCore — analytic collapse.
//
// Key identities exploited (all verified against the reference semantics):
//  * CRX blocks are no-ops; only RY blocks (params [0..10] and [22..32]) act.
//  * RY gates commute across qubits and add angles on the same qubit, so each
//    token unitary is a product state rotation with half-angle
//    h[t][q] = (A[t][q] + A[t][q+22]) / 2, where A = emb @ W.T + b.
//  * _apply_lcu's norm prefactor cancels (norm * U(m/norm) == U m), so:
//      m1 = sum_s  lam_s          * Prod(h_s)
//      m2 = sum_ts lam_t lam_s    * Prod(h_t + h_s)
//    acc = c0*e0 + c1*m1 + c2*m2  -> 21 weighted product states.
//  * poly_norm and the final state normalization cancel in exps = raw/||acc||^2.
//  * Feed-forward unitary folds in as +h_ff[q] on every term.
//  * Expectations factorize over qubits: per pair (a,b),
//      d_q = ca*cb + sa*sb,  X_q = ca*sb + sa*cb,
//      Y elem = i*(sa*cb - ca*sb),  Z_q = ca*cb - sa*sb,
//    contribution = W_pair * P_q * Prod_{q'!=q} d_{q'}.

namespace {

constexpr int NQ    = 11;
constexpr int NT    = 21;    // 1 + 4 + 16 product-state terms
constexpr int NPAIR = 231;   // NT*(NT+1)/2

__global__ void __launch_bounds__(1024, 1) quixer_kernel(
    const float* __restrict__ emb,   // [32,512]
    const float* __restrict__ W,     // [44,512]
    const float* __restrict__ bias,  // [44]
    const float* __restrict__ qc,    // [3]
    const float* __restrict__ lre,   // [32]
    const float* __restrict__ lim,   // [32]
    const float* __restrict__ ffp,   // [44]
    float* __restrict__ out)         // [33]
{
    __shared__ float rawA[4][22];        // A[t][jj], jj<11 -> param jj, else jj+11
    __shared__ float hh[4][NQ];          // combined half-angles per token
    __shared__ float sc[NT][NQ];         // cos of term half-angle
    __shared__ float ss[NT][NQ];         // sin of term half-angle
    __shared__ float wre[NT], wim[NT];   // complex term weights
    __shared__ float S_sh;               // sum |lcu| (clipped)
    __shared__ float part[34][8];        // per-warp reduction partials

    const int tid  = threadIdx.x;
    const int lane = tid & 31;
    const int wid  = tid >> 5;

    // ---- Phase A (warps 1..31 heavy): 88 dot products, one warp each ----
    // Warp 0 concurrently computes the lcu normalizer so its DRAM latency
    // overlaps the dot-product wave.
    if (wid == 0) {
        float v = hypotf(lre[lane], lim[lane]);   // 32 tokens -> one per lane
        #pragma unroll
        for (int o = 16; o; o >>= 1) v += __shfl_xor_sync(0xffffffffu, v, o);
        if (lane == 0) S_sh = fmaxf(v, 1e-8f);
    }
    for (int dd = wid; dd < 88; dd += 32) {
        const int t  = dd / 22;
        const int jj = dd - t * 22;
        const int j  = (jj < NQ) ? jj : (jj + 11);   // params 0..10 and 22..32
        const float4* e4 = reinterpret_cast<const float4*>(emb + t * 512);
        const float4* w4 = reinterpret_cast<const float4*>(W + j * 512);
        float s = 0.f;
        #pragma unroll
        for (int k = 0; k < 4; k++) {
            float4 a = e4[lane + 32 * k];
            float4 b = w4[lane + 32 * k];
            s = fmaf(a.x, b.x, s);
            s = fmaf(a.y, b.y, s);
            s = fmaf(a.z, b.z, s);
            s = fmaf(a.w, b.w, s);
        }
        #pragma unroll
        for (int o = 16; o; o >>= 1) s += __shfl_xor_sync(0xffffffffu, s, o);
        if (lane == 0) rawA[t][jj] = s + bias[j];
    }
    __syncthreads();

    // ---- Phase B1: combined half-angles ----
    if (tid < 4 * NQ) {
        int t = tid / NQ, q = tid - t * NQ;
        hh[t][q] = 0.5f * (rawA[t][q] + rawA[t][q + 11]);
    }
    __syncthreads();

    // ---- Phase B2: per-term (cos,sin) tables and complex weights ----
    if (tid < NT * NQ) {
        int term = tid / NQ, q = tid - term * NQ;
        float h = 0.5f * (ffp[q] + ffp[q + 22]);       // ff unitary folded in
        if (term >= 1 && term < 5) {
            h += hh[term - 1][q];
        } else if (term >= 5) {
            int idx = term - 5;
            h += hh[idx >> 2][q] + hh[idx & 3][q];
        }
        float cv, sv;
        sincosf(h, &sv, &cv);
        sc[term][q] = cv;
        ss[term][q] = sv;
    }
    if (tid >= 256 && tid < 256 + NT) {
        int m = tid - 256;
        float invS = 1.f / S_sh;
        float re, im;
        if (m == 0) {
            re = qc[0]; im = 0.f;
        } else if (m < 5) {
            int s = m - 1;
            float q1 = qc[1];
            re = q1 * lre[s] * invS;
            im = q1 * lim[s] * invS;
        } else {
            int idx = m - 5;
            int t = idx >> 2, s = idx & 3;
            float ar = lre[t] * invS, ai = lim[t] * invS;
            float br = lre[s] * invS, bi = lim[s] * invS;
            float q2 = qc[2];
            re = q2 * (ar * br - ai * bi);
            im = q2 * (ar * bi + ai * br);
        }
        wre[m] = re;
        wim[m] = im;
    }
    __syncthreads();

    // ---- Phase C: 231 term pairs, one per thread (warps 0..7) ----
    if (wid < 8) {
        const int p = tid;
        const bool valid = (p < NPAIR);
        int a = 0, b = 0;
        if (valid) {
            int rem = p;
            while (rem >= NT - a) { rem -= NT - a; a++; }
            b = a + rem;                       // a <= b
        }

        float d[NQ], pre[NQ + 1];
        pre[0] = 1.f;
        #pragma unroll
        for (int q = 0; q < NQ; q++) {
            float cav = sc[a][q], sav = ss[a][q];
            float cbv = sc[b][q], sbv = ss[b][q];
            d[q] = cav * cbv + sav * sbv;
            pre[q + 1] = pre[q] * d[q];
        }

        float Wr, Wy;
        if (!valid) {
            Wr = 0.f; Wy = 0.f;
        } else if (a == b) {
            Wr = wre[a] * wre[a] + wim[a] * wim[a];   // |w_a|^2
            Wy = 0.f;
        } else {
            Wr =  2.f * (wre[a] * wre[b] + wim[a] * wim[b]);  //  2 Re(conj(wa) wb)
            Wy = -2.f * (wre[a] * wim[b] - wim[a] * wre[b]);  // -2 Im(conj(wa) wb)
        }

        float vals[34];
        vals[0] = Wr * pre[NQ];                 // ||acc||^2 contribution
        float suf = 1.f;
        #pragma unroll
        for (int q = NQ - 1; q >= 0; q--) {
            float cav = sc[a][q], sav = ss[a][q];
            float cbv = sc[b][q], sbv = ss[b][q];
            float mm = pre[q] * suf;            // Prod_{q' != q} d_{q'}
            vals[1 + 3 * q + 0] = Wr * (cav * sbv + sav * cbv) * mm;  // X
            vals[1 + 3 * q + 1] = Wy * (sav * cbv - cav * sbv) * mm;  // Y
            vals[1 + 3 * q + 2] = Wr * (cav * cbv - sav * sbv) * mm;  // Z
            suf *= d[q];
        }

        // warp-level deterministic tree reduction of all 34 scalars
        #pragma unroll
        for (int m = 0; m < 34; m++) {
            float v = vals[m];
            #pragma unroll
            for (int o = 16; o; o >>= 1) v += __shfl_xor_sync(0xffffffffu, v, o);
            if (lane == 0) part[m][wid] = v;
        }
    }
    __syncthreads();

    // ---- Phase D: each output thread folds numerator AND denominator ----
    // (redundant denominator sum per thread, but removes a barrier + smem trip)
    if (tid < 33) {
        float num = 0.f, den = 0.f;
        #pragma unroll
        for (int k = 0; k < 8; k++) {
            num += part[tid + 1][k];
            den += part[0][k];
        }
        out[tid] = num / den;
    }
}

}  // namespace

extern "C" void kernel_launch(void* const* d_in, const int* in_sizes, int n_in,
                              void* d_out, int out_size) {
    (void)in_sizes; (void)n_in; (void)out_size;
    quixer_kernel<<<1, 1024>>>(
        (const float*)d_in[0],   // tokens_emb [32,512]
        (const float*)d_in[1],   // W_angles   [44,512]
        (const float*)d_in[2],   // b_angles   [44]
        (const float*)d_in[3],   // qsvt_coeffs[3]
        (const float*)d_in[4],   // lcu_re     [32]
        (const float*)d_in[5],   // lcu_im     [32]
        (const float*)d_in[6],   // ff_params  [44]
        (float*)d_out);          // [33]
}